// round 1
// baseline (speedup 1.0000x reference)
#include <cuda_runtime.h>
#include <cstddef>

#define NN 50000
#define EE 1600000
#define QQ 16
#define EPSV 1e-8f

// Scratch (allocation-free rule: __device__ globals)
__device__ float g_t2a[(size_t)EE * QQ];   // temp2 buffer A
__device__ float g_t2b[(size_t)EE * QQ];   // temp2 buffer B
__device__ float g_accum[NN * QQ];         // segment-sum accumulator
__device__ float g_marg[NN * QQ];          // node marginals

// ---------------------------------------------------------------------------
// Fused edge kernel.
// FIRST=true : cav comes from the input cav_ij tensor (step 1's matmul).
// FIRST=false: cav = softmax(marg[a1_src[e]] - t2_cur[indice[e]]) computed in
//              registers (fuses step d's cav update with step d+1's matmul).
// Then: t2_next[e] = log(cav @ C + eps); red.v4 into accum[edge_dst[e]].
// ---------------------------------------------------------------------------
template <bool FIRST>
__global__ void __launch_bounds__(256)
edge_kernel(const float* __restrict__ cav_in,
            const float* __restrict__ marg,
            const float* __restrict__ t2_cur,
            float* __restrict__ t2_next,
            const int* __restrict__ a1_src,
            const int* __restrict__ indice,
            const int* __restrict__ edge_dst,
            const float* __restrict__ Cmat,
            float* __restrict__ accum)
{
    __shared__ __align__(16) float Cs[QQ][QQ];
    const int t = threadIdx.x;
    if (t < (QQ * QQ) / 4) {
        ((float4*)&Cs[0][0])[t] = ((const float4*)Cmat)[t];
    }
    __syncthreads();

    const int e = blockIdx.x * blockDim.x + t;
    if (e >= EE) return;

    float cav[QQ];

    if (FIRST) {
        const float4* cp = (const float4*)(cav_in + (size_t)e * QQ);
#pragma unroll
        for (int g = 0; g < 4; g++) {
            float4 v = cp[g];
            cav[4 * g + 0] = v.x; cav[4 * g + 1] = v.y;
            cav[4 * g + 2] = v.z; cav[4 * g + 3] = v.w;
        }
    } else {
        const int s = a1_src[e];
        const int j = indice[e];
        const float4* mp = (const float4*)(marg + (size_t)s * QQ);
        const float4* tp = (const float4*)(t2_cur + (size_t)j * QQ);
#pragma unroll
        for (int g = 0; g < 4; g++) {
            float4 mv = mp[g];
            float4 tv = tp[g];
            cav[4 * g + 0] = mv.x - tv.x; cav[4 * g + 1] = mv.y - tv.y;
            cav[4 * g + 2] = mv.z - tv.z; cav[4 * g + 3] = mv.w - tv.w;
        }
        // softmax over the 16 values, in registers
        float mx = cav[0];
#pragma unroll
        for (int q = 1; q < QQ; q++) mx = fmaxf(mx, cav[q]);
        float ssum = 0.0f;
#pragma unroll
        for (int q = 0; q < QQ; q++) {
            cav[q] = __expf(cav[q] - mx);
            ssum += cav[q];
        }
        const float inv = 1.0f / ssum;
#pragma unroll
        for (int q = 0; q < QQ; q++) cav[q] *= inv;
    }

    // temp2 = log(cav @ C + eps)
    float acc[QQ];
#pragma unroll
    for (int q = 0; q < QQ; q++) acc[q] = EPSV;
#pragma unroll
    for (int k = 0; k < QQ; k++) {
        const float ck = cav[k];
        const float4* crow = (const float4*)Cs[k];
#pragma unroll
        for (int g = 0; g < 4; g++) {
            float4 c = crow[g];
            acc[4 * g + 0] += ck * c.x;
            acc[4 * g + 1] += ck * c.y;
            acc[4 * g + 2] += ck * c.z;
            acc[4 * g + 3] += ck * c.w;
        }
    }

    float4 o[4];
#pragma unroll
    for (int g = 0; g < 4; g++) {
        o[g].x = __logf(acc[4 * g + 0]);
        o[g].y = __logf(acc[4 * g + 1]);
        o[g].z = __logf(acc[4 * g + 2]);
        o[g].w = __logf(acc[4 * g + 3]);
    }

    float4* op = (float4*)(t2_next + (size_t)e * QQ);
#pragma unroll
    for (int g = 0; g < 4; g++) op[g] = o[g];

    // segment-sum into destination node via vector reductions (stay in L2)
    const int d = edge_dst[e];
    float* ap = accum + (size_t)d * QQ;
#pragma unroll
    for (int g = 0; g < 4; g++) {
        asm volatile("red.global.add.v4.f32 [%0], {%1,%2,%3,%4};"
                     :: "l"(ap + 4 * g),
                        "f"(o[g].x), "f"(o[g].y), "f"(o[g].z), "f"(o[g].w)
                     : "memory");
    }
}

// marg = accum + field; accum = 0 (ready for the next edge pass)
__global__ void __launch_bounds__(256)
node_kernel(const float* __restrict__ field,
            float* __restrict__ marg,
            float* __restrict__ accum)
{
    const int i = blockIdx.x * blockDim.x + threadIdx.x;
    if (i >= (NN * QQ) / 4) return;
    float4 a = ((const float4*)accum)[i];
    float4 f = ((const float4*)field)[i];
    float4 m;
    m.x = a.x + f.x; m.y = a.y + f.y; m.z = a.z + f.z; m.w = a.w + f.w;
    ((float4*)marg)[i] = m;
    float4 z = make_float4(0.f, 0.f, 0.f, 0.f);
    ((float4*)accum)[i] = z;
}

// out = log_softmax(marg, axis=1)
__global__ void __launch_bounds__(256)
out_kernel(const float* __restrict__ marg, float* __restrict__ out)
{
    const int n = blockIdx.x * blockDim.x + threadIdx.x;
    if (n >= NN) return;
    float x[QQ];
    const float4* mp = (const float4*)(marg + (size_t)n * QQ);
#pragma unroll
    for (int g = 0; g < 4; g++) {
        float4 v = mp[g];
        x[4 * g + 0] = v.x; x[4 * g + 1] = v.y;
        x[4 * g + 2] = v.z; x[4 * g + 3] = v.w;
    }
    float mx = x[0];
#pragma unroll
    for (int q = 1; q < QQ; q++) mx = fmaxf(mx, x[q]);
    float s = 0.0f;
#pragma unroll
    for (int q = 0; q < QQ; q++) s += __expf(x[q] - mx);
    const float lse = mx + __logf(s);
    float4* op = (float4*)(out + (size_t)n * QQ);
#pragma unroll
    for (int g = 0; g < 4; g++) {
        float4 v;
        v.x = x[4 * g + 0] - lse; v.y = x[4 * g + 1] - lse;
        v.z = x[4 * g + 2] - lse; v.w = x[4 * g + 3] - lse;
        op[g] = v;
    }
}

extern "C" void kernel_launch(void* const* d_in, const int* in_sizes, int n_in,
                              void* d_out, int out_size)
{
    // metadata order: marg_i(unused), cav_ij, C, field_i, edge_dst, a1_src, indice_ij
    const float* cav_ij   = (const float*)d_in[1];
    const float* Cmat     = (const float*)d_in[2];
    const float* field_i  = (const float*)d_in[3];
    const int*   edge_dst = (const int*)d_in[4];
    const int*   a1_src   = (const int*)d_in[5];
    const int*   indice   = (const int*)d_in[6];
    float*       out      = (float*)d_out;

    float *accum, *marg, *t2a, *t2b;
    cudaGetSymbolAddress((void**)&accum, g_accum);
    cudaGetSymbolAddress((void**)&marg,  g_marg);
    cudaGetSymbolAddress((void**)&t2a,   g_t2a);
    cudaGetSymbolAddress((void**)&t2b,   g_t2b);

    cudaMemsetAsync(accum, 0, (size_t)NN * QQ * sizeof(float));

    const int EB = 256;
    const int EG = (EE + EB - 1) / EB;
    const int NB = 256;
    const int NG = ((NN * QQ) / 4 + NB - 1) / NB;
    const int OG = (NN + NB - 1) / NB;

    // step 1 matmul (cav from input)
    edge_kernel<true><<<EG, EB>>>(cav_ij, marg, t2a, t2a,
                                  a1_src, indice, edge_dst, Cmat, accum);

    const float* cur = t2a;
    float* nxt = t2b;
    // steps 1..4: node update, then fused (cav softmax of step d + matmul of step d+1)
    for (int d = 0; d < 4; d++) {
        node_kernel<<<NG, NB>>>(field_i, marg, accum);
        edge_kernel<false><<<EG, EB>>>(nullptr, marg, cur, nxt,
                                       a1_src, indice, edge_dst, Cmat, accum);
        float* tmp = (float*)cur; cur = nxt; nxt = tmp;
    }
    // step 5 node update (final marg) + output
    node_kernel<<<NG, NB>>>(field_i, marg, accum);
    out_kernel<<<OG, NB>>>(marg, out);
}

// round 2
// speedup vs baseline: 1.2170x; 1.2170x over previous
#include <cuda_runtime.h>
#include <cuda_fp16.h>
#include <cstddef>

#define NN 50000
#define EE 1600000
#define QQ 16
#define EPSV 1e-8f

// Scratch (allocation-free rule: __device__ globals)
// temp2 stored as fp16: 16 halves = 32 B per edge -> 51.2 MB per buffer.
// Both ping-pong buffers (102.4 MB) fit in the 126 MB L2 -> gather becomes L2-hit.
__device__ __align__(16) __half2 g_t2a[(size_t)EE * 8];
__device__ __align__(16) __half2 g_t2b[(size_t)EE * 8];
__device__ float g_accum[NN * QQ];
__device__ float g_marg[NN * QQ];

// ---------------------------------------------------------------------------
// Fused edge kernel.
// FIRST=true : cav comes from the input cav_ij tensor (step 1's matmul).
// FIRST=false: cav = softmax(marg[a1_src[e]] - t2_cur[indice[e]]) in registers
//              (fuses step d's cav update with step d+1's matmul).
// Then: t2_next[e] = fp16(log(cav @ C + eps)); red.v4 (fp32) into accum[dst].
// Segment-sum precision is unaffected by fp16 storage (uses register fp32).
// ---------------------------------------------------------------------------
template <bool FIRST>
__global__ void __launch_bounds__(256)
edge_kernel(const float* __restrict__ cav_in,
            const float* __restrict__ marg,
            const __half2* __restrict__ t2_cur,
            __half2* __restrict__ t2_next,
            const int* __restrict__ a1_src,
            const int* __restrict__ indice,
            const int* __restrict__ edge_dst,
            const float* __restrict__ Cmat,
            float* __restrict__ accum)
{
    __shared__ __align__(16) float Cs[QQ][QQ];
    const int t = threadIdx.x;
    if (t < (QQ * QQ) / 4) {
        ((float4*)&Cs[0][0])[t] = ((const float4*)Cmat)[t];
    }
    __syncthreads();

    const int e = blockIdx.x * blockDim.x + t;
    if (e >= EE) return;

    float cav[QQ];

    if (FIRST) {
        // streamed once; keep out of L2 (evict-first)
        const float4* cp = (const float4*)(cav_in + (size_t)e * QQ);
#pragma unroll
        for (int g = 0; g < 4; g++) {
            float4 v = __ldcs(cp + g);
            cav[4 * g + 0] = v.x; cav[4 * g + 1] = v.y;
            cav[4 * g + 2] = v.z; cav[4 * g + 3] = v.w;
        }
    } else {
        const int s = __ldcs(a1_src + e);
        const int j = __ldcs(indice + e);
        const float4* mp = (const float4*)(marg + (size_t)s * QQ);
        const uint4*  tp = (const uint4*)(t2_cur + (size_t)j * 8);
        uint4 u0 = tp[0];
        uint4 u1 = tp[1];
        const __half2* h0 = (const __half2*)&u0;
        const __half2* h1 = (const __half2*)&u1;
#pragma unroll
        for (int g = 0; g < 2; g++) {
            float4 mv = mp[g];
            float2 t0 = __half22float2(h0[2 * g + 0]);
            float2 t1 = __half22float2(h0[2 * g + 1]);
            cav[4 * g + 0] = mv.x - t0.x; cav[4 * g + 1] = mv.y - t0.y;
            cav[4 * g + 2] = mv.z - t1.x; cav[4 * g + 3] = mv.w - t1.y;
        }
#pragma unroll
        for (int g = 0; g < 2; g++) {
            float4 mv = mp[2 + g];
            float2 t0 = __half22float2(h1[2 * g + 0]);
            float2 t1 = __half22float2(h1[2 * g + 1]);
            cav[8 + 4 * g + 0] = mv.x - t0.x; cav[8 + 4 * g + 1] = mv.y - t0.y;
            cav[8 + 4 * g + 2] = mv.z - t1.x; cav[8 + 4 * g + 3] = mv.w - t1.y;
        }
        // softmax over the 16 values, in registers
        float mx = cav[0];
#pragma unroll
        for (int q = 1; q < QQ; q++) mx = fmaxf(mx, cav[q]);
        float ssum = 0.0f;
#pragma unroll
        for (int q = 0; q < QQ; q++) {
            cav[q] = __expf(cav[q] - mx);
            ssum += cav[q];
        }
        const float inv = 1.0f / ssum;
#pragma unroll
        for (int q = 0; q < QQ; q++) cav[q] *= inv;
    }

    // temp2 = log(cav @ C + eps)
    float acc[QQ];
#pragma unroll
    for (int q = 0; q < QQ; q++) acc[q] = EPSV;
#pragma unroll
    for (int k = 0; k < QQ; k++) {
        const float ck = cav[k];
        const float4* crow = (const float4*)Cs[k];
#pragma unroll
        for (int g = 0; g < 4; g++) {
            float4 c = crow[g];
            acc[4 * g + 0] += ck * c.x;
            acc[4 * g + 1] += ck * c.y;
            acc[4 * g + 2] += ck * c.z;
            acc[4 * g + 3] += ck * c.w;
        }
    }

    float o[QQ];
#pragma unroll
    for (int q = 0; q < QQ; q++) o[q] = __logf(acc[q]);

    // store fp16 temp2 (32 B per edge)
    __align__(16) __half2 hh[8];
#pragma unroll
    for (int p = 0; p < 8; p++)
        hh[p] = __floats2half2_rn(o[2 * p + 0], o[2 * p + 1]);
    uint4* op = (uint4*)(t2_next + (size_t)e * 8);
    op[0] = ((uint4*)hh)[0];
    op[1] = ((uint4*)hh)[1];

    // segment-sum into destination node (fp32 register values -> exact path)
    const int d = __ldcs(edge_dst + e);
    float* ap = accum + (size_t)d * QQ;
#pragma unroll
    for (int g = 0; g < 4; g++) {
        asm volatile("red.global.add.v4.f32 [%0], {%1,%2,%3,%4};"
                     :: "l"(ap + 4 * g),
                        "f"(o[4 * g + 0]), "f"(o[4 * g + 1]),
                        "f"(o[4 * g + 2]), "f"(o[4 * g + 3])
                     : "memory");
    }
}

// marg = accum + field; accum = 0 (ready for the next edge pass)
__global__ void __launch_bounds__(256)
node_kernel(const float* __restrict__ field,
            float* __restrict__ marg,
            float* __restrict__ accum)
{
    const int i = blockIdx.x * blockDim.x + threadIdx.x;
    if (i >= (NN * QQ) / 4) return;
    float4 a = ((const float4*)accum)[i];
    float4 f = ((const float4*)field)[i];
    float4 m;
    m.x = a.x + f.x; m.y = a.y + f.y; m.z = a.z + f.z; m.w = a.w + f.w;
    ((float4*)marg)[i] = m;
    ((float4*)accum)[i] = make_float4(0.f, 0.f, 0.f, 0.f);
}

// out = log_softmax(marg, axis=1)
__global__ void __launch_bounds__(256)
out_kernel(const float* __restrict__ marg, float* __restrict__ out)
{
    const int n = blockIdx.x * blockDim.x + threadIdx.x;
    if (n >= NN) return;
    float x[QQ];
    const float4* mp = (const float4*)(marg + (size_t)n * QQ);
#pragma unroll
    for (int g = 0; g < 4; g++) {
        float4 v = mp[g];
        x[4 * g + 0] = v.x; x[4 * g + 1] = v.y;
        x[4 * g + 2] = v.z; x[4 * g + 3] = v.w;
    }
    float mx = x[0];
#pragma unroll
    for (int q = 1; q < QQ; q++) mx = fmaxf(mx, x[q]);
    float s = 0.0f;
#pragma unroll
    for (int q = 0; q < QQ; q++) s += __expf(x[q] - mx);
    const float lse = mx + __logf(s);
    float4* op = (float4*)(out + (size_t)n * QQ);
#pragma unroll
    for (int g = 0; g < 4; g++) {
        float4 v;
        v.x = x[4 * g + 0] - lse; v.y = x[4 * g + 1] - lse;
        v.z = x[4 * g + 2] - lse; v.w = x[4 * g + 3] - lse;
        op[g] = v;
    }
}

extern "C" void kernel_launch(void* const* d_in, const int* in_sizes, int n_in,
                              void* d_out, int out_size)
{
    // metadata order: marg_i(unused), cav_ij, C, field_i, edge_dst, a1_src, indice_ij
    const float* cav_ij   = (const float*)d_in[1];
    const float* Cmat     = (const float*)d_in[2];
    const float* field_i  = (const float*)d_in[3];
    const int*   edge_dst = (const int*)d_in[4];
    const int*   a1_src   = (const int*)d_in[5];
    const int*   indice   = (const int*)d_in[6];
    float*       out      = (float*)d_out;

    float *accum, *marg;
    __half2 *t2a, *t2b;
    cudaGetSymbolAddress((void**)&accum, g_accum);
    cudaGetSymbolAddress((void**)&marg,  g_marg);
    cudaGetSymbolAddress((void**)&t2a,   g_t2a);
    cudaGetSymbolAddress((void**)&t2b,   g_t2b);

    cudaMemsetAsync(accum, 0, (size_t)NN * QQ * sizeof(float));

    const int EB = 256;
    const int EG = (EE + EB - 1) / EB;
    const int NB = 256;
    const int NG = ((NN * QQ) / 4 + NB - 1) / NB;
    const int OG = (NN + NB - 1) / NB;

    // step 1 matmul (cav from input)
    edge_kernel<true><<<EG, EB>>>(cav_ij, marg, t2a, t2a,
                                  a1_src, indice, edge_dst, Cmat, accum);

    const __half2* cur = t2a;
    __half2* nxt = t2b;
    // steps 1..4: node update, then fused (cav softmax of step d + matmul of step d+1)
    for (int d = 0; d < 4; d++) {
        node_kernel<<<NG, NB>>>(field_i, marg, accum);
        edge_kernel<false><<<EG, EB>>>(nullptr, marg, cur, nxt,
                                       a1_src, indice, edge_dst, Cmat, accum);
        __half2* tmp = (__half2*)cur; cur = nxt; nxt = tmp;
    }
    // step 5 node update (final marg) + output
    node_kernel<<<NG, NB>>>(field_i, marg, accum);
    out_kernel<<<OG, NB>>>(marg, out);
}

// round 3
// speedup vs baseline: 1.2732x; 1.0462x over previous
#include <cuda_runtime.h>
#include <cuda_fp16.h>
#include <cstddef>
#include <cstdint>

#define NN 50000
#define EE 1600000
#define HALF_E (EE / 2)
#define QQ 16
#define EPSV 1e-8f

// Scratch (allocation-free rule: __device__ globals)
// temp2 stored as fp16: 32 B per edge -> 51.2 MB per buffer; both fit in L2.
__device__ __align__(16) __half2 g_t2a[(size_t)EE * 8];
__device__ __align__(16) __half2 g_t2b[(size_t)EE * 8];
__device__ float g_accum[NN * QQ];
__device__ float g_marg[NN * QQ];

// Packed f32x2 helpers (sm_100+; ptxas never emits FFMA2 from C++)
#define FFMA2(d, a, b, c) \
    asm("fma.rn.f32x2 %0, %1, %2, %3;" : "=l"(d) : "l"(a), "l"(b), "l"(c))
#define PACK2(d, lo, hi) \
    asm("mov.b64 %0, {%1, %2};" : "=l"(d) : "f"(lo), "f"(hi))
#define UNPACK2(lo, hi, s) \
    asm("mov.b64 {%0, %1}, %2;" : "=f"(lo), "=f"(hi) : "l"(s))

// ---------------------------------------------------------------------------
// Fused edge kernel, 2 edges per thread (e and e+HALF_E).
// FIRST=true : cav from input tensor (no softmax), inv = 1.
// FIRST=false: raw = exp(marg[a1_src] - t2_cur[indice] - mx) in registers;
//              normalization folded into epilogue via inv = 1/sum.
// Matmul: acc = raw @ C with FFMA2, C rows loaded ONCE per k for both edges.
// temp2 = log(acc*inv + eps) -> fp16 store + fp32 red.v4 into accum[dst].
// ---------------------------------------------------------------------------
template <bool FIRST>
__global__ void __launch_bounds__(256)
edge_kernel(const float* __restrict__ cav_in,
            const float* __restrict__ marg,
            const __half2* __restrict__ t2_cur,
            __half2* __restrict__ t2_next,
            const int* __restrict__ a1_src,
            const int* __restrict__ indice,
            const int* __restrict__ edge_dst,
            const float* __restrict__ Cmat,
            float* __restrict__ accum)
{
    __shared__ __align__(16) float Cs[QQ][QQ];
    const int t = threadIdx.x;
    if (t < (QQ * QQ) / 4) {
        ((float4*)&Cs[0][0])[t] = ((const float4*)Cmat)[t];
    }
    __syncthreads();

    const int e0 = blockIdx.x * blockDim.x + t;      // < HALF_E (exact grid)
    const int e1 = e0 + HALF_E;

    float r0[QQ], r1[QQ];     // matmul inputs (unnormalized)
    float inv0, inv1;         // per-edge normalization factor

    if (FIRST) {
        const float4* p0 = (const float4*)(cav_in + (size_t)e0 * QQ);
        const float4* p1 = (const float4*)(cav_in + (size_t)e1 * QQ);
#pragma unroll
        for (int g = 0; g < 4; g++) {
            float4 a = __ldcs(p0 + g);
            float4 b = __ldcs(p1 + g);
            r0[4*g+0]=a.x; r0[4*g+1]=a.y; r0[4*g+2]=a.z; r0[4*g+3]=a.w;
            r1[4*g+0]=b.x; r1[4*g+1]=b.y; r1[4*g+2]=b.z; r1[4*g+3]=b.w;
        }
        inv0 = 1.0f; inv1 = 1.0f;
    } else {
        const int s0 = __ldcs(a1_src + e0);
        const int s1 = __ldcs(a1_src + e1);
        const int j0 = __ldcs(indice + e0);
        const int j1 = __ldcs(indice + e1);
        const float4* mp0 = (const float4*)(marg + (size_t)s0 * QQ);
        const float4* mp1 = (const float4*)(marg + (size_t)s1 * QQ);
        const uint4*  tp0 = (const uint4*)(t2_cur + (size_t)j0 * 8);
        const uint4*  tp1 = (const uint4*)(t2_cur + (size_t)j1 * 8);
        uint4 u0a = tp0[0], u0b = tp0[1];
        uint4 u1a = tp1[0], u1b = tp1[1];
        const __half2* h0 = (const __half2*)&u0a;   // [0..3] then u0b
        const __half2* h1 = (const __half2*)&u1a;
#pragma unroll
        for (int g = 0; g < 4; g++) {
            float4 m0 = mp0[g];
            float4 m1 = mp1[g];
            const __half2* q0 = (g < 2) ? h0 + 2*g : ((const __half2*)&u0b) + 2*(g-2);
            const __half2* q1 = (g < 2) ? h1 + 2*g : ((const __half2*)&u1b) + 2*(g-2);
            float2 ta = __half22float2(q0[0]);
            float2 tb = __half22float2(q0[1]);
            r0[4*g+0]=m0.x-ta.x; r0[4*g+1]=m0.y-ta.y; r0[4*g+2]=m0.z-tb.x; r0[4*g+3]=m0.w-tb.y;
            float2 tc = __half22float2(q1[0]);
            float2 td = __half22float2(q1[1]);
            r1[4*g+0]=m1.x-tc.x; r1[4*g+1]=m1.y-tc.y; r1[4*g+2]=m1.z-td.x; r1[4*g+3]=m1.w-td.y;
        }
        float mx0 = r0[0], mx1 = r1[0];
#pragma unroll
        for (int q = 1; q < QQ; q++) { mx0 = fmaxf(mx0, r0[q]); mx1 = fmaxf(mx1, r1[q]); }
        float s0s = 0.f, s1s = 0.f;
#pragma unroll
        for (int q = 0; q < QQ; q++) {
            r0[q] = __expf(r0[q] - mx0); s0s += r0[q];
            r1[q] = __expf(r1[q] - mx1); s1s += r1[q];
        }
        inv0 = 1.0f / s0s;
        inv1 = 1.0f / s1s;
    }

    // acc = r @ C   (packed f32x2, C row loaded once for both edges)
    unsigned long long acc0[8], acc1[8];
    {
        unsigned long long z; PACK2(z, 0.0f, 0.0f);
#pragma unroll
        for (int j = 0; j < 8; j++) { acc0[j] = z; acc1[j] = z; }
    }
    uint32_t cs_base = (uint32_t)__cvta_generic_to_shared(&Cs[0][0]);
#pragma unroll
    for (int k = 0; k < QQ; k++) {
        unsigned long long c0, c1, c2, c3, c4, c5, c6, c7;
        uint32_t row = cs_base + k * 64;
        asm volatile("ld.shared.v2.u64 {%0,%1}, [%2];"    : "=l"(c0), "=l"(c1) : "r"(row));
        asm volatile("ld.shared.v2.u64 {%0,%1}, [%2+16];" : "=l"(c2), "=l"(c3) : "r"(row));
        asm volatile("ld.shared.v2.u64 {%0,%1}, [%2+32];" : "=l"(c4), "=l"(c5) : "r"(row));
        asm volatile("ld.shared.v2.u64 {%0,%1}, [%2+48];" : "=l"(c6), "=l"(c7) : "r"(row));
        unsigned long long k0, k1;
        PACK2(k0, r0[k], r0[k]);
        PACK2(k1, r1[k], r1[k]);
        FFMA2(acc0[0], k0, c0, acc0[0]); FFMA2(acc1[0], k1, c0, acc1[0]);
        FFMA2(acc0[1], k0, c1, acc0[1]); FFMA2(acc1[1], k1, c1, acc1[1]);
        FFMA2(acc0[2], k0, c2, acc0[2]); FFMA2(acc1[2], k1, c2, acc1[2]);
        FFMA2(acc0[3], k0, c3, acc0[3]); FFMA2(acc1[3], k1, c3, acc1[3]);
        FFMA2(acc0[4], k0, c4, acc0[4]); FFMA2(acc1[4], k1, c4, acc1[4]);
        FFMA2(acc0[5], k0, c5, acc0[5]); FFMA2(acc1[5], k1, c5, acc1[5]);
        FFMA2(acc0[6], k0, c6, acc0[6]); FFMA2(acc1[6], k1, c6, acc1[6]);
        FFMA2(acc0[7], k0, c7, acc0[7]); FFMA2(acc1[7], k1, c7, acc1[7]);
    }

    // epilogue: temp2 = log(acc*inv + eps), fp16 store, fp32 red into accum
    unsigned long long eps2, i0, i1;
    PACK2(eps2, EPSV, EPSV);
    PACK2(i0, inv0, inv0);
    PACK2(i1, inv1, inv1);

    float o0[QQ], o1[QQ];
#pragma unroll
    for (int j = 0; j < 8; j++) {
        unsigned long long v0, v1;
        FFMA2(v0, acc0[j], i0, eps2);
        FFMA2(v1, acc1[j], i1, eps2);
        float a, b;
        UNPACK2(a, b, v0); o0[2*j] = __logf(a); o0[2*j+1] = __logf(b);
        UNPACK2(a, b, v1); o1[2*j] = __logf(a); o1[2*j+1] = __logf(b);
    }

    __align__(16) __half2 hh[8];
#pragma unroll
    for (int p = 0; p < 8; p++) hh[p] = __floats2half2_rn(o0[2*p], o0[2*p+1]);
    uint4* w0 = (uint4*)(t2_next + (size_t)e0 * 8);
    w0[0] = ((uint4*)hh)[0]; w0[1] = ((uint4*)hh)[1];
#pragma unroll
    for (int p = 0; p < 8; p++) hh[p] = __floats2half2_rn(o1[2*p], o1[2*p+1]);
    uint4* w1 = (uint4*)(t2_next + (size_t)e1 * 8);
    w1[0] = ((uint4*)hh)[0]; w1[1] = ((uint4*)hh)[1];

    const int d0 = __ldcs(edge_dst + e0);
    const int d1 = __ldcs(edge_dst + e1);
    float* a0 = accum + (size_t)d0 * QQ;
    float* a1 = accum + (size_t)d1 * QQ;
#pragma unroll
    for (int g = 0; g < 4; g++) {
        asm volatile("red.global.add.v4.f32 [%0], {%1,%2,%3,%4};"
                     :: "l"(a0 + 4*g), "f"(o0[4*g]), "f"(o0[4*g+1]),
                        "f"(o0[4*g+2]), "f"(o0[4*g+3]) : "memory");
        asm volatile("red.global.add.v4.f32 [%0], {%1,%2,%3,%4};"
                     :: "l"(a1 + 4*g), "f"(o1[4*g]), "f"(o1[4*g+1]),
                        "f"(o1[4*g+2]), "f"(o1[4*g+3]) : "memory");
    }
}

// marg = accum + field; accum = 0
__global__ void __launch_bounds__(256)
node_kernel(const float* __restrict__ field,
            float* __restrict__ marg,
            float* __restrict__ accum)
{
    const int i = blockIdx.x * blockDim.x + threadIdx.x;
    if (i >= (NN * QQ) / 4) return;
    float4 a = ((const float4*)accum)[i];
    float4 f = ((const float4*)field)[i];
    ((float4*)marg)[i] = make_float4(a.x + f.x, a.y + f.y, a.z + f.z, a.w + f.w);
    ((float4*)accum)[i] = make_float4(0.f, 0.f, 0.f, 0.f);
}

// out = log_softmax(marg, axis=1)
__global__ void __launch_bounds__(256)
out_kernel(const float* __restrict__ marg, float* __restrict__ out)
{
    const int n = blockIdx.x * blockDim.x + threadIdx.x;
    if (n >= NN) return;
    float x[QQ];
    const float4* mp = (const float4*)(marg + (size_t)n * QQ);
#pragma unroll
    for (int g = 0; g < 4; g++) {
        float4 v = mp[g];
        x[4*g]=v.x; x[4*g+1]=v.y; x[4*g+2]=v.z; x[4*g+3]=v.w;
    }
    float mx = x[0];
#pragma unroll
    for (int q = 1; q < QQ; q++) mx = fmaxf(mx, x[q]);
    float s = 0.0f;
#pragma unroll
    for (int q = 0; q < QQ; q++) s += __expf(x[q] - mx);
    const float lse = mx + __logf(s);
    float4* op = (float4*)(out + (size_t)n * QQ);
#pragma unroll
    for (int g = 0; g < 4; g++)
        op[g] = make_float4(x[4*g]-lse, x[4*g+1]-lse, x[4*g+2]-lse, x[4*g+3]-lse);
}

extern "C" void kernel_launch(void* const* d_in, const int* in_sizes, int n_in,
                              void* d_out, int out_size)
{
    // metadata order: marg_i(unused), cav_ij, C, field_i, edge_dst, a1_src, indice_ij
    const float* cav_ij   = (const float*)d_in[1];
    const float* Cmat     = (const float*)d_in[2];
    const float* field_i  = (const float*)d_in[3];
    const int*   edge_dst = (const int*)d_in[4];
    const int*   a1_src   = (const int*)d_in[5];
    const int*   indice   = (const int*)d_in[6];
    float*       out      = (float*)d_out;

    float *accum, *marg;
    __half2 *t2a, *t2b;
    cudaGetSymbolAddress((void**)&accum, g_accum);
    cudaGetSymbolAddress((void**)&marg,  g_marg);
    cudaGetSymbolAddress((void**)&t2a,   g_t2a);
    cudaGetSymbolAddress((void**)&t2b,   g_t2b);

    cudaMemsetAsync(accum, 0, (size_t)NN * QQ * sizeof(float));

    const int EB = 256;
    const int EG = HALF_E / EB;           // 800000 / 256 = 3125 exact
    const int NB = 256;
    const int NG = ((NN * QQ) / 4 + NB - 1) / NB;
    const int OG = (NN + NB - 1) / NB;

    edge_kernel<true><<<EG, EB>>>(cav_ij, marg, t2a, t2a,
                                  a1_src, indice, edge_dst, Cmat, accum);

    const __half2* cur = t2a;
    __half2* nxt = t2b;
    for (int d = 0; d < 4; d++) {
        node_kernel<<<NG, NB>>>(field_i, marg, accum);
        edge_kernel<false><<<EG, EB>>>(nullptr, marg, cur, nxt,
                                       a1_src, indice, edge_dst, Cmat, accum);
        __half2* tmp = (__half2*)cur; cur = nxt; nxt = tmp;
    }
    node_kernel<<<NG, NB>>>(field_i, marg, accum);
    out_kernel<<<OG, NB>>>(marg, out);
}